// round 12
// baseline (speedup 1.0000x reference)
#include <cuda_runtime.h>
#include <cuda_fp16.h>
#include <cstdint>

#define B_  4
#define T_  2048
#define D_  1024
#define H_  16
#define M_  (B_*T_)   // 8192

// Scratch (__device__ globals — allocation rules forbid cudaMalloc)
__device__ __half g_xh[(size_t)M_*D_];        // x in fp16
__device__ __half g_qh[(size_t)B_*H_*T_*64];  // (B,H,T,64) fp16, pre-scaled by 1/8
__device__ __half g_kh[(size_t)B_*H_*T_*64];
__device__ __half g_vh[(size_t)B_*H_*T_*64];
__device__ __half g_ctxh[(size_t)M_*D_];      // (B,T,D) fp16
__device__ __half g_wth[(size_t)4*D_*D_];     // W^T fp16: [4][N][K] (Wq pre-scaled 1/8)

__device__ __forceinline__ float neg_inf() { return __int_as_float(0xff800000u); }

__device__ __forceinline__ uint32_t packh2(float x, float y) {
    __half2 h = __floats2half2_rn(x, y);
    return *(uint32_t*)&h;
}

__device__ __forceinline__ uint32_t smem_u32(const void* p) {
    uint32_t a;
    asm("{ .reg .u64 t; cvta.to.shared.u64 t, %1; cvt.u32.u64 %0, t; }" : "=r"(a) : "l"(p));
    return a;
}

#define CP16(dst, src) \
    asm volatile("cp.async.cg.shared.global [%0], [%1], 16;" :: "r"(dst), "l"(src))
#define CP_COMMIT() asm volatile("cp.async.commit_group;" ::: "memory")
#define CP_WAIT(n)  asm volatile("cp.async.wait_group %0;" :: "n"(n) : "memory")

__device__ __forceinline__ void mma_f16(float* d, const uint32_t* a, const uint32_t* b) {
    asm volatile(
        "mma.sync.aligned.m16n8k16.row.col.f32.f16.f16.f32 "
        "{%0,%1,%2,%3}, {%4,%5,%6,%7}, {%8,%9}, {%0,%1,%2,%3};"
        : "+f"(d[0]), "+f"(d[1]), "+f"(d[2]), "+f"(d[3])
        : "r"(a[0]), "r"(a[1]), "r"(a[2]), "r"(a[3]), "r"(b[0]), "r"(b[1]));
}

__device__ __forceinline__ void ldsm4(uint32_t* r, uint32_t addr) {
    asm volatile("ldmatrix.sync.aligned.m8n8.x4.shared.b16 {%0,%1,%2,%3}, [%4];"
        : "=r"(r[0]), "=r"(r[1]), "=r"(r[2]), "=r"(r[3]) : "r"(addr));
}
__device__ __forceinline__ void ldsm4t(uint32_t* r, uint32_t addr) {
    asm volatile("ldmatrix.sync.aligned.m8n8.x4.trans.shared.b16 {%0,%1,%2,%3}, [%4];"
        : "=r"(r[0]), "=r"(r[1]), "=r"(r[2]), "=r"(r[3]) : "r"(addr));
}

// ---------------------------------------------------------------------------
// x -> fp16
// ---------------------------------------------------------------------------
__global__ void __launch_bounds__(256) convert_x(const float* __restrict__ x)
{
    const size_t i = ((size_t)blockIdx.x * 256 + threadIdx.x) * 8;
    float4 a = *(const float4*)(x + i);
    float4 b = *(const float4*)(x + i + 4);
    uint4 o;
    o.x = packh2(a.x, a.y); o.y = packh2(a.z, a.w);
    o.z = packh2(b.x, b.y); o.w = packh2(b.z, b.w);
    *(uint4*)(g_xh + i) = o;
}

// ---------------------------------------------------------------------------
// Weight transpose + fp16 round (Wq pre-scaled by 1/8)
// ---------------------------------------------------------------------------
__global__ void __launch_bounds__(256) transpose_w(
    const float* __restrict__ W0, const float* __restrict__ W1,
    const float* __restrict__ W2, const float* __restrict__ W3)
{
    __shared__ float tile[32][33];
    const int z = blockIdx.z;
    const float* W = z == 0 ? W0 : z == 1 ? W1 : z == 2 ? W2 : W3;
    const float sc = (z == 0) ? 0.125f : 1.f;
    __half* out = g_wth + (size_t)z * D_ * D_;
    const int k0 = blockIdx.x * 32, n0 = blockIdx.y * 32;
    const int tx = threadIdx.x & 31, ty = threadIdx.x >> 5;
#pragma unroll
    for (int i = 0; i < 32; i += 8)
        tile[ty + i][tx] = W[(size_t)(k0 + ty + i) * D_ + n0 + tx];
    __syncthreads();
#pragma unroll
    for (int i = 0; i < 32; i += 8)
        out[(size_t)(n0 + ty + i) * D_ + k0 + tx] = __float2half_rn(tile[tx][ty + i] * sc);
}

// ---------------------------------------------------------------------------
// fp16 GEMM, cp.async 3-stage + ldmatrix frags: C[M,1024] = A*W + bias*bscale
// BM=BN=128, BK=32; 8 warps (2x4), warp tile 64x32.
// ---------------------------------------------------------------------------
#define GST_H  (128*40)          // halves per operand per stage
#define GST_B  (2*GST_H*2)       // bytes per stage (A+B) = 20480
#define GEMM_DYN (3*GST_B)       // 61440

template<int MODE>
__device__ __forceinline__ void gemm_cp(
    const __half* __restrict__ A, const __half* __restrict__ Wt,
    const float* __restrict__ bias, float bscale, void* __restrict__ outv)
{
    extern __shared__ __half smh[];
    const uint32_t smb = smem_u32(smh);

    const int t    = threadIdx.x;
    const int lane = t & 31;
    const int w    = t >> 5;
    const int g    = lane >> 2;
    const int tig  = lane & 3;
    const int wm   = (w >> 2) * 64;
    const int wn   = (w & 3) * 32;
    const int m0   = blockIdx.y * 128;
    const int n0   = blockIdx.x * 128;

    // ldmatrix per-lane row/col adds
    const int mat = lane >> 3, mr = lane & 7;
    const int a_rowadd = ((mat & 1) << 3) + mr;   // A-frag: mats {rlo,rhi,rlo,rhi}
    const int a_koff   = (mat >> 1) << 3;         //         k    {lo, lo, hi, hi}
    const int b_rowadd = ((mat >> 1) << 3) + mr;  // B-frag pair: {na,na,nb,nb}
    const int b_koff   = (mat & 1) << 3;          //             k{lo,hi,lo,hi}

    float acc[4][4][4];
#pragma unroll
    for (int mt = 0; mt < 4; mt++)
#pragma unroll
        for (int nt = 0; nt < 4; nt++)
#pragma unroll
            for (int i = 0; i < 4; i++) acc[mt][nt][i] = 0.f;

#define GFILL(s, k0c) do { \
        const uint32_t ab = smb + (s) * GST_B; \
_Pragma("unroll") \
        for (int i = 0; i < 2; i++) { \
            const int ci  = t + i * 256; \
            const int row = ci >> 2, seg = (ci & 3) * 8; \
            CP16(ab + row * 80 + seg * 2, A  + (size_t)(m0 + row) * D_ + (k0c) + seg); \
            CP16(ab + GST_H * 2 + row * 80 + seg * 2, \
                 Wt + (size_t)(n0 + row) * D_ + (k0c) + seg); \
        } \
    } while (0)

    GFILL(0, 0);  CP_COMMIT();
    GFILL(1, 32); CP_COMMIT();

    for (int kt = 0; kt < 32; kt++) {
        const int s = kt % 3;
        if (kt >= 30) CP_WAIT(0); else CP_WAIT(1);
        __syncthreads();
        if (kt + 2 < 32) { GFILL((kt + 2) % 3, (kt + 2) * 32); CP_COMMIT(); }

        const uint32_t as = smb + s * GST_B;
        const uint32_t bs = as + GST_H * 2;
#pragma unroll
        for (int kk = 0; kk < 2; kk++) {
            const int k = kk * 16;
            uint32_t a[4][4], b[2][4];
#pragma unroll
            for (int mt = 0; mt < 4; mt++)
                ldsm4(a[mt], as + 2 * ((wm + mt * 16 + a_rowadd) * 40 + k + a_koff));
#pragma unroll
            for (int p = 0; p < 2; p++)
                ldsm4(b[p], bs + 2 * ((wn + p * 16 + b_rowadd) * 40 + k + b_koff));
#pragma unroll
            for (int mt = 0; mt < 4; mt++)
#pragma unroll
                for (int p = 0; p < 2; p++) {
                    mma_f16(acc[mt][2 * p],     a[mt], b[p]);
                    mma_f16(acc[mt][2 * p + 1], a[mt], b[p] + 2);
                }
        }
        __syncthreads();
    }
#undef GFILL

    // Epilogue
#pragma unroll
    for (int mt = 0; mt < 4; mt++) {
        const int r = m0 + wm + mt * 16 + g;
#pragma unroll
        for (int nt = 0; nt < 4; nt++) {
            const int c = n0 + wn + nt * 8 + 2 * tig;
            const float b0 = bias[c] * bscale, b1 = bias[c + 1] * bscale;
            const float v00 = acc[mt][nt][0] + b0, v01 = acc[mt][nt][1] + b1;
            const float v10 = acc[mt][nt][2] + b0, v11 = acc[mt][nt][3] + b1;
            if (MODE == 0) {
                __half* out = (__half*)outv;
                const int h = c >> 6, dd = c & 63;
                const int b0i = r >> 11, tt0 = r & (T_ - 1);
                *(uint32_t*)&out[(((size_t)(b0i * H_ + h) * T_ + tt0) << 6) + dd] =
                    packh2(v00, v01);
                const int r1 = r + 8;
                const int b1i = r1 >> 11, tt1 = r1 & (T_ - 1);
                *(uint32_t*)&out[(((size_t)(b1i * H_ + h) * T_ + tt1) << 6) + dd] =
                    packh2(v10, v11);
            } else {
                float* out = (float*)outv;
                *(float2*)&out[(size_t)r * D_ + c] = make_float2(v00, v01);
                *(float2*)&out[(size_t)(r + 8) * D_ + c] = make_float2(v10, v11);
            }
        }
    }
}

__global__ void __launch_bounds__(256) qkv_kernel(
    const float* __restrict__ bq, const float* __restrict__ bk,
    const float* __restrict__ bv)
{
    const int z = blockIdx.z;
    const __half* Wt = g_wth + (size_t)z * D_ * D_;
    const float* bias = z == 0 ? bq : z == 1 ? bk : bv;
    __half* out = z == 0 ? g_qh : z == 1 ? g_kh : g_vh;
    gemm_cp<0>(g_xh, Wt, bias, z == 0 ? 0.125f : 1.f, out);
}

__global__ void __launch_bounds__(256) oproj_kernel(
    const float* __restrict__ bo, float* __restrict__ out)
{
    gemm_cp<1>(g_ctxh, g_wth + (size_t)3 * D_ * D_, bo, 1.f, out);
}

// ---------------------------------------------------------------------------
// Flash attention: fp16 MMA + ldmatrix + cp.async double-buffered KV.
// Block: 128 queries x one (b,h); 8 warps x 16 rows. 64-key tiles.
// P stays in registers (S C-frag == PV A-frag layout). V via ldmatrix.trans.
// smem: Qs[128][72] + 2 stages x (Ks[64][72] + Vs[64][72]) = 55296 B
// ---------------------------------------------------------------------------
#define AQ_H  72
#define AKV_H 72
#define AQ_B  (128*AQ_H*2)          // 18432
#define AST_B (2*64*AKV_H*2)        // 18432 per stage (K+V)
#define AV_OFF (64*AKV_H*2)         // V offset within stage
#define ATTN_SMEM (AQ_B + 2*AST_B)  // 55296

__global__ void __launch_bounds__(256, 2) attn_kernel()
{
    extern __shared__ __half smh[];
    const uint32_t smb = smem_u32(smh);
    __half* Qs = smh;

    const int t    = threadIdx.x;
    const int lane = t & 31;
    const int w    = t >> 5;
    const int g    = lane >> 2;
    const int tig  = lane & 3;
    const int qb   = (int)gridDim.x - 1 - (int)blockIdx.x;   // big tiles first
    const int bh   = blockIdx.y;
    const size_t base = (size_t)bh * T_ * 64;
    const int pr   = w * 16 + g;
    const int qr   = qb * 128 + pr;

    const int mat = lane >> 3, mr = lane & 7;
    const int a_rowadd = ((mat & 1) << 3) + mr;
    const int a_koff   = (mat >> 1) << 3;
    const int b_rowadd = ((mat >> 1) << 3) + mr;
    const int b_koff   = (mat & 1) << 3;

    // KV tile fill via cp.async into stage s
#define KVFILL(s, kb) do { \
        const uint32_t kb_ = smb + AQ_B + (s) * AST_B; \
_Pragma("unroll") \
        for (int i = 0; i < 2; i++) { \
            const int idx = t + i * 256; \
            const int row = idx >> 3, seg = (idx & 7) * 8; \
            CP16(kb_ + row * (AKV_H * 2) + seg * 2, \
                 g_kh + base + (size_t)((kb) * 64 + row) * 64 + seg); \
            CP16(kb_ + AV_OFF + row * (AKV_H * 2) + seg * 2, \
                 g_vh + base + (size_t)((kb) * 64 + row) * 64 + seg); \
        } \
    } while (0)

    const int kbmax = 2 * qb + 1;

    // Prefetch tile 0 first so DRAM latency overlaps Q staging
    KVFILL(0, 0); CP_COMMIT();

    // Stage Q (pre-scaled fp16)
#pragma unroll
    for (int i = 0; i < 4; i++) {
        const int idx = t + i * 256;
        const int r = idx >> 3, seg = (idx & 7) * 8;
        *(uint4*)&Qs[r * AQ_H + seg] =
            *(const uint4*)(g_qh + base + (size_t)(qb * 128 + r) * 64 + seg);
    }
    __syncthreads();

    uint32_t qa[4][4];
#pragma unroll
    for (int kk = 0; kk < 4; kk++)
        ldsm4(qa[kk], smb + 2 * ((w * 16 + a_rowadd) * AQ_H + kk * 16 + a_koff));

    float o[8][4];
#pragma unroll
    for (int nt = 0; nt < 8; nt++)
#pragma unroll
        for (int i = 0; i < 4; i++) o[nt][i] = 0.f;
    float m0r = neg_inf(), m1r = neg_inf(), l0 = 0.f, l1 = 0.f;

    for (int kb = 0; kb <= kbmax; kb++) {
        if (kb < kbmax) { KVFILL((kb + 1) & 1, kb + 1); CP_COMMIT(); }
        if (kb < kbmax) CP_WAIT(1); else CP_WAIT(0);
        __syncthreads();

        const uint32_t ks = smb + AQ_B + (kb & 1) * AST_B;
        const uint32_t vs = ks + AV_OFF;

        // S = Q K^T
        float s[8][4];
#pragma unroll
        for (int nt = 0; nt < 8; nt++)
#pragma unroll
            for (int i = 0; i < 4; i++) s[nt][i] = 0.f;
#pragma unroll
        for (int kk = 0; kk < 4; kk++) {
            const int k = kk * 16;
#pragma unroll
            for (int p = 0; p < 4; p++) {
                uint32_t kbf[4];
                ldsm4(kbf, ks + 2 * ((p * 16 + b_rowadd) * AKV_H + k + b_koff));
                mma_f16(s[2 * p],     qa[kk], kbf);
                mma_f16(s[2 * p + 1], qa[kk], kbf + 2);
            }
        }

        // Causal mask (diagonal key blocks only)
        if (kb >= 2 * qb) {
            const int r0g = qr, r1g = qr + 8;
#pragma unroll
            for (int nt = 0; nt < 8; nt++) {
                const int j0 = kb * 64 + nt * 8 + 2 * tig;
                if (j0 > r0g)     s[nt][0] = neg_inf();
                if (j0 + 1 > r0g) s[nt][1] = neg_inf();
                if (j0 > r1g)     s[nt][2] = neg_inf();
                if (j0 + 1 > r1g) s[nt][3] = neg_inf();
            }
        }

        // Online softmax (rows g, g+8; 4-lane shfl groups)
        float mx0 = neg_inf(), mx1 = neg_inf();
#pragma unroll
        for (int nt = 0; nt < 8; nt++) {
            mx0 = fmaxf(mx0, fmaxf(s[nt][0], s[nt][1]));
            mx1 = fmaxf(mx1, fmaxf(s[nt][2], s[nt][3]));
        }
        mx0 = fmaxf(mx0, __shfl_xor_sync(0xffffffffu, mx0, 1));
        mx0 = fmaxf(mx0, __shfl_xor_sync(0xffffffffu, mx0, 2));
        mx1 = fmaxf(mx1, __shfl_xor_sync(0xffffffffu, mx1, 1));
        mx1 = fmaxf(mx1, __shfl_xor_sync(0xffffffffu, mx1, 2));

        const float mn0 = fmaxf(m0r, mx0), mn1 = fmaxf(m1r, mx1);
        const float a0 = __expf(m0r - mn0), a1 = __expf(m1r - mn1);
        m0r = mn0; m1r = mn1;

        float rs0 = 0.f, rs1 = 0.f;
#pragma unroll
        for (int nt = 0; nt < 8; nt++) {
            s[nt][0] = __expf(s[nt][0] - mn0);
            s[nt][1] = __expf(s[nt][1] - mn0);
            s[nt][2] = __expf(s[nt][2] - mn1);
            s[nt][3] = __expf(s[nt][3] - mn1);
            rs0 += s[nt][0] + s[nt][1];
            rs1 += s[nt][2] + s[nt][3];
        }
        rs0 += __shfl_xor_sync(0xffffffffu, rs0, 1);
        rs0 += __shfl_xor_sync(0xffffffffu, rs0, 2);
        rs1 += __shfl_xor_sync(0xffffffffu, rs1, 1);
        rs1 += __shfl_xor_sync(0xffffffffu, rs1, 2);
        l0 = l0 * a0 + rs0;
        l1 = l1 * a1 + rs1;

#pragma unroll
        for (int nt = 0; nt < 8; nt++) {
            o[nt][0] *= a0; o[nt][1] *= a0;
            o[nt][2] *= a1; o[nt][3] *= a1;
        }

        // O += P V : P packed straight from S registers (C-frag == A-frag layout)
#pragma unroll
        for (int kk = 0; kk < 4; kk++) {
            uint32_t pa[4];
            pa[0] = packh2(s[2 * kk][0],     s[2 * kk][1]);
            pa[1] = packh2(s[2 * kk][2],     s[2 * kk][3]);
            pa[2] = packh2(s[2 * kk + 1][0], s[2 * kk + 1][1]);
            pa[3] = packh2(s[2 * kk + 1][2], s[2 * kk + 1][3]);
            const int k = kk * 16;
#pragma unroll
            for (int p = 0; p < 4; p++) {
                uint32_t vbf[4];
                ldsm4t(vbf, vs + 2 * ((k + a_rowadd) * AKV_H + p * 16 + a_koff));
                mma_f16(o[2 * p],     pa, vbf);
                mma_f16(o[2 * p + 1], pa, vbf + 2);
            }
        }
        __syncthreads();   // all warps done reading this stage before it is refilled
    }
#undef KVFILL

    // Epilogue: normalize + write ctx fp16 (B,T,D)
    const int bb = bh >> 4, h = bh & 15;
    const float i0 = 1.f / l0, i1 = 1.f / l1;
#pragma unroll
    for (int nt = 0; nt < 8; nt++) {
        const int d = h * 64 + nt * 8 + 2 * tig;
        *(uint32_t*)&g_ctxh[(size_t)(bb * T_ + qr) * D_ + d] =
            packh2(o[nt][0] * i0, o[nt][1] * i0);
        *(uint32_t*)&g_ctxh[(size_t)(bb * T_ + qr + 8) * D_ + d] =
            packh2(o[nt][2] * i1, o[nt][3] * i1);
    }
}

// ---------------------------------------------------------------------------
extern "C" void kernel_launch(void* const* d_in, const int* in_sizes, int n_in,
                              void* d_out, int out_size)
{
    (void)in_sizes; (void)n_in; (void)out_size;
    const float* x  = (const float*)d_in[0];
    const float* Wq = (const float*)d_in[1];
    const float* bq = (const float*)d_in[2];
    const float* Wk = (const float*)d_in[3];
    const float* bk = (const float*)d_in[4];
    const float* Wv = (const float*)d_in[5];
    const float* bv = (const float*)d_in[6];
    const float* Wo = (const float*)d_in[7];
    const float* bo = (const float*)d_in[8];
    float* out = (float*)d_out;

    convert_x<<<M_ * D_ / (256 * 8), 256>>>(x);
    transpose_w<<<dim3(D_ / 32, D_ / 32, 4), 256>>>(Wq, Wk, Wv, Wo);

    cudaFuncSetAttribute(qkv_kernel, cudaFuncAttributeMaxDynamicSharedMemorySize, GEMM_DYN);
    qkv_kernel<<<dim3(D_ / 128, M_ / 128, 3), 256, GEMM_DYN>>>(bq, bk, bv);

    cudaFuncSetAttribute(attn_kernel, cudaFuncAttributeMaxDynamicSharedMemorySize, ATTN_SMEM);
    attn_kernel<<<dim3(T_ / 128, B_ * H_), 256, ATTN_SMEM>>>();

    cudaFuncSetAttribute(oproj_kernel, cudaFuncAttributeMaxDynamicSharedMemorySize, GEMM_DYN);
    oproj_kernel<<<dim3(D_ / 128, M_ / 128), 256, GEMM_DYN>>>(bo, out);
}

// round 13
// speedup vs baseline: 1.4886x; 1.4886x over previous
#include <cuda_runtime.h>
#include <cuda_fp16.h>
#include <cstdint>

#define B_  4
#define T_  2048
#define D_  1024
#define H_  16
#define M_  (B_*T_)   // 8192

#define QSCALE (0.125f * 1.44269504f)   // 1/sqrt(64) * log2(e): softmax in log2 domain

// Scratch (__device__ globals — allocation rules forbid cudaMalloc)
__device__ __half g_xh[(size_t)M_*D_];        // x in fp16
__device__ __half g_qh[(size_t)B_*H_*T_*64];  // (B,H,T,64) fp16, pre-scaled by QSCALE
__device__ __half g_kh[(size_t)B_*H_*T_*64];
__device__ __half g_vh[(size_t)B_*H_*T_*64];
__device__ __half g_ctxh[(size_t)M_*D_];      // (B,T,D) fp16
__device__ __half g_wth[(size_t)4*D_*D_];     // W^T fp16: [4][N][K] (Wq pre-scaled QSCALE)

__device__ __forceinline__ float neg_inf() { return __int_as_float(0xff800000u); }

__device__ __forceinline__ float ex2f(float x) {   // single MUFU.EX2 (same unit __expf uses)
    float r;
    asm("ex2.approx.ftz.f32 %0, %1;" : "=f"(r) : "f"(x));
    return r;
}

__device__ __forceinline__ uint32_t packh2(float x, float y) {
    __half2 h = __floats2half2_rn(x, y);
    return *(uint32_t*)&h;
}

__device__ __forceinline__ uint32_t smem_u32(const void* p) {
    uint32_t a;
    asm("{ .reg .u64 t; cvta.to.shared.u64 t, %1; cvt.u32.u64 %0, t; }" : "=r"(a) : "l"(p));
    return a;
}

#define CP16(dst, src) \
    asm volatile("cp.async.cg.shared.global [%0], [%1], 16;" :: "r"(dst), "l"(src))
#define CP_COMMIT() asm volatile("cp.async.commit_group;" ::: "memory")
#define CP_WAIT(n)  asm volatile("cp.async.wait_group %0;" :: "n"(n) : "memory")

__device__ __forceinline__ void mma_f16(float* d, const uint32_t* a, const uint32_t* b) {
    asm volatile(
        "mma.sync.aligned.m16n8k16.row.col.f32.f16.f16.f32 "
        "{%0,%1,%2,%3}, {%4,%5,%6,%7}, {%8,%9}, {%0,%1,%2,%3};"
        : "+f"(d[0]), "+f"(d[1]), "+f"(d[2]), "+f"(d[3])
        : "r"(a[0]), "r"(a[1]), "r"(a[2]), "r"(a[3]), "r"(b[0]), "r"(b[1]));
}

__device__ __forceinline__ void ldsm4(uint32_t* r, uint32_t addr) {
    asm volatile("ldmatrix.sync.aligned.m8n8.x4.shared.b16 {%0,%1,%2,%3}, [%4];"
        : "=r"(r[0]), "=r"(r[1]), "=r"(r[2]), "=r"(r[3]) : "r"(addr));
}
__device__ __forceinline__ void ldsm4t(uint32_t* r, uint32_t addr) {
    asm volatile("ldmatrix.sync.aligned.m8n8.x4.trans.shared.b16 {%0,%1,%2,%3}, [%4];"
        : "=r"(r[0]), "=r"(r[1]), "=r"(r[2]), "=r"(r[3]) : "r"(addr));
}

// ---------------------------------------------------------------------------
// x -> fp16
// ---------------------------------------------------------------------------
__global__ void __launch_bounds__(256) convert_x(const float* __restrict__ x)
{
    const size_t i = ((size_t)blockIdx.x * 256 + threadIdx.x) * 8;
    float4 a = *(const float4*)(x + i);
    float4 b = *(const float4*)(x + i + 4);
    uint4 o;
    o.x = packh2(a.x, a.y); o.y = packh2(a.z, a.w);
    o.z = packh2(b.x, b.y); o.w = packh2(b.z, b.w);
    *(uint4*)(g_xh + i) = o;
}

// ---------------------------------------------------------------------------
// Weight transpose + fp16 round (Wq pre-scaled by QSCALE)
// ---------------------------------------------------------------------------
__global__ void __launch_bounds__(256) transpose_w(
    const float* __restrict__ W0, const float* __restrict__ W1,
    const float* __restrict__ W2, const float* __restrict__ W3)
{
    __shared__ float tile[32][33];
    const int z = blockIdx.z;
    const float* W = z == 0 ? W0 : z == 1 ? W1 : z == 2 ? W2 : W3;
    const float sc = (z == 0) ? QSCALE : 1.f;
    __half* out = g_wth + (size_t)z * D_ * D_;
    const int k0 = blockIdx.x * 32, n0 = blockIdx.y * 32;
    const int tx = threadIdx.x & 31, ty = threadIdx.x >> 5;
#pragma unroll
    for (int i = 0; i < 32; i += 8)
        tile[ty + i][tx] = W[(size_t)(k0 + ty + i) * D_ + n0 + tx];
    __syncthreads();
#pragma unroll
    for (int i = 0; i < 32; i += 8)
        out[(size_t)(n0 + ty + i) * D_ + k0 + tx] = __float2half_rn(tile[tx][ty + i] * sc);
}

// ---------------------------------------------------------------------------
// fp16 GEMM, cp.async 3-stage, DIRECT uint32 frag loads (R10 proven-fast form)
// BM=BN=128, BK=32; 8 warps (2x4), warp tile 64x32.
// ---------------------------------------------------------------------------
#define GST_H  (128*40)          // halves per operand per stage
#define GST_B  (2*GST_H*2)       // bytes per stage (A+B) = 20480
#define GEMM_DYN (3*GST_B)       // 61440

template<int MODE>
__device__ __forceinline__ void gemm_cp(
    const __half* __restrict__ A, const __half* __restrict__ Wt,
    const float* __restrict__ bias, float bscale, void* __restrict__ outv)
{
    extern __shared__ __half smh[];
    const uint32_t smb = smem_u32(smh);

    const int t    = threadIdx.x;
    const int lane = t & 31;
    const int w    = t >> 5;
    const int g    = lane >> 2;
    const int tig  = lane & 3;
    const int wm   = (w >> 2) * 64;
    const int wn   = (w & 3) * 32;
    const int m0   = blockIdx.y * 128;
    const int n0   = blockIdx.x * 128;

    float acc[4][4][4];
#pragma unroll
    for (int mt = 0; mt < 4; mt++)
#pragma unroll
        for (int nt = 0; nt < 4; nt++)
#pragma unroll
            for (int i = 0; i < 4; i++) acc[mt][nt][i] = 0.f;

#define GFILL(s, k0c) do { \
        const uint32_t ab = smb + (s) * GST_B; \
_Pragma("unroll") \
        for (int i = 0; i < 2; i++) { \
            const int ci  = t + i * 256; \
            const int row = ci >> 2, seg = (ci & 3) * 8; \
            CP16(ab + row * 80 + seg * 2, A  + (size_t)(m0 + row) * D_ + (k0c) + seg); \
            CP16(ab + GST_H * 2 + row * 80 + seg * 2, \
                 Wt + (size_t)(n0 + row) * D_ + (k0c) + seg); \
        } \
    } while (0)

    GFILL(0, 0);  CP_COMMIT();
    GFILL(1, 32); CP_COMMIT();

    for (int kt = 0; kt < 32; kt++) {
        const int s = kt % 3;
        if (kt >= 30) CP_WAIT(0); else CP_WAIT(1);
        __syncthreads();
        if (kt + 2 < 32) { GFILL((kt + 2) % 3, (kt + 2) * 32); CP_COMMIT(); }

        const __half* As = smh + s * (2 * GST_H);
        const __half* Bs = As + GST_H;
#pragma unroll
        for (int kk = 0; kk < 2; kk++) {
            const int k = kk * 16;
            uint32_t a[4][4], b[4][2];
#pragma unroll
            for (int mt = 0; mt < 4; mt++) {
                const int r = wm + mt * 16 + g;
                a[mt][0] = *(const uint32_t*)&As[r * 40 + k + 2 * tig];
                a[mt][1] = *(const uint32_t*)&As[(r + 8) * 40 + k + 2 * tig];
                a[mt][2] = *(const uint32_t*)&As[r * 40 + k + 2 * tig + 8];
                a[mt][3] = *(const uint32_t*)&As[(r + 8) * 40 + k + 2 * tig + 8];
            }
#pragma unroll
            for (int nt = 0; nt < 4; nt++) {
                const int c = wn + nt * 8 + g;
                b[nt][0] = *(const uint32_t*)&Bs[c * 40 + k + 2 * tig];
                b[nt][1] = *(const uint32_t*)&Bs[c * 40 + k + 2 * tig + 8];
            }
#pragma unroll
            for (int mt = 0; mt < 4; mt++)
#pragma unroll
                for (int nt = 0; nt < 4; nt++)
                    mma_f16(acc[mt][nt], a[mt], b[nt]);
        }
        __syncthreads();
    }
#undef GFILL

    // Epilogue
#pragma unroll
    for (int mt = 0; mt < 4; mt++) {
        const int r = m0 + wm + mt * 16 + g;
#pragma unroll
        for (int nt = 0; nt < 4; nt++) {
            const int c = n0 + wn + nt * 8 + 2 * tig;
            const float b0 = bias[c] * bscale, b1 = bias[c + 1] * bscale;
            const float v00 = acc[mt][nt][0] + b0, v01 = acc[mt][nt][1] + b1;
            const float v10 = acc[mt][nt][2] + b0, v11 = acc[mt][nt][3] + b1;
            if (MODE == 0) {
                __half* out = (__half*)outv;
                const int h = c >> 6, dd = c & 63;
                const int b0i = r >> 11, tt0 = r & (T_ - 1);
                *(uint32_t*)&out[(((size_t)(b0i * H_ + h) * T_ + tt0) << 6) + dd] =
                    packh2(v00, v01);
                const int r1 = r + 8;
                const int b1i = r1 >> 11, tt1 = r1 & (T_ - 1);
                *(uint32_t*)&out[(((size_t)(b1i * H_ + h) * T_ + tt1) << 6) + dd] =
                    packh2(v10, v11);
            } else {
                float* out = (float*)outv;
                *(float2*)&out[(size_t)r * D_ + c] = make_float2(v00, v01);
                *(float2*)&out[(size_t)(r + 8) * D_ + c] = make_float2(v10, v11);
            }
        }
    }
}

__global__ void __launch_bounds__(256) qkv_kernel(
    const float* __restrict__ bq, const float* __restrict__ bk,
    const float* __restrict__ bv)
{
    const int z = blockIdx.z;
    const __half* Wt = g_wth + (size_t)z * D_ * D_;
    const float* bias = z == 0 ? bq : z == 1 ? bk : bv;
    __half* out = z == 0 ? g_qh : z == 1 ? g_kh : g_vh;
    gemm_cp<0>(g_xh, Wt, bias, z == 0 ? QSCALE : 1.f, out);
}

__global__ void __launch_bounds__(256) oproj_kernel(
    const float* __restrict__ bo, float* __restrict__ out)
{
    gemm_cp<1>(g_ctxh, g_wth + (size_t)3 * D_ * D_, bo, 1.f, out);
}

// ---------------------------------------------------------------------------
// Flash attention (R11 form: ldmatrix + register P + cp.async double buffer),
// softmax in log2 domain (Q pre-scaled by QSCALE, exp -> single MUFU.EX2).
// Block: 128 queries x one (b,h); 8 warps x 16 rows; 64-key tiles.
// smem: Qs[128][72] + 2 stages x (Ks[64][72] + Vs[64][72]) = 55296 B
// ---------------------------------------------------------------------------
#define AQ_H  72
#define AKV_H 72
#define AQ_B  (128*AQ_H*2)          // 18432
#define AST_B (2*64*AKV_H*2)        // 18432 per stage (K+V)
#define AV_OFF (64*AKV_H*2)
#define ATTN_SMEM (AQ_B + 2*AST_B)  // 55296

__global__ void __launch_bounds__(256, 2) attn_kernel()
{
    extern __shared__ __half smh[];
    const uint32_t smb = smem_u32(smh);
    __half* Qs = smh;

    const int t    = threadIdx.x;
    const int lane = t & 31;
    const int w    = t >> 5;
    const int g    = lane >> 2;
    const int tig  = lane & 3;
    const int qb   = (int)gridDim.x - 1 - (int)blockIdx.x;   // big tiles first
    const int bh   = blockIdx.y;
    const size_t base = (size_t)bh * T_ * 64;
    const int pr   = w * 16 + g;
    const int qr   = qb * 128 + pr;

    const int mat = lane >> 3, mr = lane & 7;
    const int a_rowadd = ((mat & 1) << 3) + mr;
    const int a_koff   = (mat >> 1) << 3;
    const int b_rowadd = ((mat >> 1) << 3) + mr;
    const int b_koff   = (mat & 1) << 3;

#define KVFILL(s, kb) do { \
        const uint32_t kb_ = smb + AQ_B + (s) * AST_B; \
_Pragma("unroll") \
        for (int i = 0; i < 2; i++) { \
            const int idx = t + i * 256; \
            const int row = idx >> 3, seg = (idx & 7) * 8; \
            CP16(kb_ + row * (AKV_H * 2) + seg * 2, \
                 g_kh + base + (size_t)((kb) * 64 + row) * 64 + seg); \
            CP16(kb_ + AV_OFF + row * (AKV_H * 2) + seg * 2, \
                 g_vh + base + (size_t)((kb) * 64 + row) * 64 + seg); \
        } \
    } while (0)

    const int kbmax = 2 * qb + 1;

    KVFILL(0, 0); CP_COMMIT();

    // Stage Q (pre-scaled fp16)
#pragma unroll
    for (int i = 0; i < 4; i++) {
        const int idx = t + i * 256;
        const int r = idx >> 3, seg = (idx & 7) * 8;
        *(uint4*)&Qs[r * AQ_H + seg] =
            *(const uint4*)(g_qh + base + (size_t)(qb * 128 + r) * 64 + seg);
    }
    __syncthreads();

    uint32_t qa[4][4];
#pragma unroll
    for (int kk = 0; kk < 4; kk++)
        ldsm4(qa[kk], smb + 2 * ((w * 16 + a_rowadd) * AQ_H + kk * 16 + a_koff));

    float o[8][4];
#pragma unroll
    for (int nt = 0; nt < 8; nt++)
#pragma unroll
        for (int i = 0; i < 4; i++) o[nt][i] = 0.f;
    float m0r = neg_inf(), m1r = neg_inf(), l0 = 0.f, l1 = 0.f;

    for (int kb = 0; kb <= kbmax; kb++) {
        if (kb < kbmax) { KVFILL((kb + 1) & 1, kb + 1); CP_COMMIT(); }
        if (kb < kbmax) CP_WAIT(1); else CP_WAIT(0);
        __syncthreads();

        const uint32_t ks = smb + AQ_B + (kb & 1) * AST_B;
        const uint32_t vs = ks + AV_OFF;

        // S = Q K^T   (scores already in log2 domain)
        float s[8][4];
#pragma unroll
        for (int nt = 0; nt < 8; nt++)
#pragma unroll
            for (int i = 0; i < 4; i++) s[nt][i] = 0.f;
#pragma unroll
        for (int kk = 0; kk < 4; kk++) {
            const int k = kk * 16;
#pragma unroll
            for (int p = 0; p < 4; p++) {
                uint32_t kbf[4];
                ldsm4(kbf, ks + 2 * ((p * 16 + b_rowadd) * AKV_H + k + b_koff));
                mma_f16(s[2 * p],     qa[kk], kbf);
                mma_f16(s[2 * p + 1], qa[kk], kbf + 2);
            }
        }

        // Causal mask (diagonal key blocks only)
        if (kb >= 2 * qb) {
            const int r0g = qr, r1g = qr + 8;
#pragma unroll
            for (int nt = 0; nt < 8; nt++) {
                const int j0 = kb * 64 + nt * 8 + 2 * tig;
                if (j0 > r0g)     s[nt][0] = neg_inf();
                if (j0 + 1 > r0g) s[nt][1] = neg_inf();
                if (j0 > r1g)     s[nt][2] = neg_inf();
                if (j0 + 1 > r1g) s[nt][3] = neg_inf();
            }
        }

        // Online softmax (log2 domain; rows g, g+8; 4-lane shfl groups)
        float mx0 = neg_inf(), mx1 = neg_inf();
#pragma unroll
        for (int nt = 0; nt < 8; nt++) {
            mx0 = fmaxf(mx0, fmaxf(s[nt][0], s[nt][1]));
            mx1 = fmaxf(mx1, fmaxf(s[nt][2], s[nt][3]));
        }
        mx0 = fmaxf(mx0, __shfl_xor_sync(0xffffffffu, mx0, 1));
        mx0 = fmaxf(mx0, __shfl_xor_sync(0xffffffffu, mx0, 2));
        mx1 = fmaxf(mx1, __shfl_xor_sync(0xffffffffu, mx1, 1));
        mx1 = fmaxf(mx1, __shfl_xor_sync(0xffffffffu, mx1, 2));

        const float mn0 = fmaxf(m0r, mx0), mn1 = fmaxf(m1r, mx1);
        const float a0 = ex2f(m0r - mn0), a1 = ex2f(m1r - mn1);
        m0r = mn0; m1r = mn1;

        float rs0 = 0.f, rs1 = 0.f;
#pragma unroll
        for (int nt = 0; nt < 8; nt++) {
            s[nt][0] = ex2f(s[nt][0] - mn0);
            s[nt][1] = ex2f(s[nt][1] - mn0);
            s[nt][2] = ex2f(s[nt][2] - mn1);
            s[nt][3] = ex2f(s[nt][3] - mn1);
            rs0 += s[nt][0] + s[nt][1];
            rs1 += s[nt][2] + s[nt][3];
        }
        rs0 += __shfl_xor_sync(0xffffffffu, rs0, 1);
        rs0 += __shfl_xor_sync(0xffffffffu, rs0, 2);
        rs1 += __shfl_xor_sync(0xffffffffu, rs1, 1);
        rs1 += __shfl_xor_sync(0xffffffffu, rs1, 2);
        l0 = l0 * a0 + rs0;
        l1 = l1 * a1 + rs1;

#pragma unroll
        for (int nt = 0; nt < 8; nt++) {
            o[nt][0] *= a0; o[nt][1] *= a0;
            o[nt][2] *= a1; o[nt][3] *= a1;
        }

        // O += P V : P packed straight from S registers (C-frag == A-frag layout)
#pragma unroll
        for (int kk = 0; kk < 4; kk++) {
            uint32_t pa[4];
            pa[0] = packh2(s[2 * kk][0],     s[2 * kk][1]);
            pa[1] = packh2(s[2 * kk][2],     s[2 * kk][3]);
            pa[2] = packh2(s[2 * kk + 1][0], s[2 * kk + 1][1]);
            pa[3] = packh2(s[2 * kk + 1][2], s[2 * kk + 1][3]);
            const int k = kk * 16;
#pragma unroll
            for (int p = 0; p < 4; p++) {
                uint32_t vbf[4];
                ldsm4t(vbf, vs + 2 * ((k + a_rowadd) * AKV_H + p * 16 + a_koff));
                mma_f16(o[2 * p],     pa, vbf);
                mma_f16(o[2 * p + 1], pa, vbf + 2);
            }
        }
        __syncthreads();   // all warps done reading this stage before it is refilled
    }
#undef KVFILL

    // Epilogue: normalize + write ctx fp16 (B,T,D)
    const int bb = bh >> 4, h = bh & 15;
    const float i0 = 1.f / l0, i1 = 1.f / l1;
#pragma unroll
    for (int nt = 0; nt < 8; nt++) {
        const int d = h * 64 + nt * 8 + 2 * tig;
        *(uint32_t*)&g_ctxh[(size_t)(bb * T_ + qr) * D_ + d] =
            packh2(o[nt][0] * i0, o[nt][1] * i0);
        *(uint32_t*)&g_ctxh[(size_t)(bb * T_ + qr + 8) * D_ + d] =
            packh2(o[nt][2] * i1, o[nt][3] * i1);
    }
}

// ---------------------------------------------------------------------------
extern "C" void kernel_launch(void* const* d_in, const int* in_sizes, int n_in,
                              void* d_out, int out_size)
{
    (void)in_sizes; (void)n_in; (void)out_size;
    const float* x  = (const float*)d_in[0];
    const float* Wq = (const float*)d_in[1];
    const float* bq = (const float*)d_in[2];
    const float* Wk = (const float*)d_in[3];
    const float* bk = (const float*)d_in[4];
    const float* Wv = (const float*)d_in[5];
    const float* bv = (const float*)d_in[6];
    const float* Wo = (const float*)d_in[7];
    const float* bo = (const float*)d_in[8];
    float* out = (float*)d_out;

    convert_x<<<M_ * D_ / (256 * 8), 256>>>(x);
    transpose_w<<<dim3(D_ / 32, D_ / 32, 4), 256>>>(Wq, Wk, Wv, Wo);

    cudaFuncSetAttribute(qkv_kernel, cudaFuncAttributeMaxDynamicSharedMemorySize, GEMM_DYN);
    qkv_kernel<<<dim3(D_ / 128, M_ / 128, 3), 256, GEMM_DYN>>>(bq, bk, bv);

    cudaFuncSetAttribute(attn_kernel, cudaFuncAttributeMaxDynamicSharedMemorySize, ATTN_SMEM);
    attn_kernel<<<dim3(T_ / 128, B_ * H_), 256, ATTN_SMEM>>>();

    cudaFuncSetAttribute(oproj_kernel, cudaFuncAttributeMaxDynamicSharedMemorySize, GEMM_DYN);
    oproj_kernel<<<dim3(D_ / 128, M_ / 128), 256, GEMM_DYN>>>(bo, out);
}

// round 15
// speedup vs baseline: 1.6838x; 1.1311x over previous
#include <cuda_runtime.h>
#include <cuda_fp16.h>
#include <cstdint>

#define B_  4
#define T_  2048
#define D_  1024
#define H_  16
#define M_  (B_*T_)   // 8192

#define QSCALE (0.125f * 1.44269504f)   // 1/sqrt(64) * log2(e): softmax in log2 domain

// Scratch (__device__ globals — allocation rules forbid cudaMalloc)
__device__ __half g_xh[(size_t)M_*D_];        // x in fp16
__device__ __half g_qh[(size_t)B_*H_*T_*64];  // (B,H,T,64) fp16, pre-scaled by QSCALE
__device__ __half g_kh[(size_t)B_*H_*T_*64];
__device__ __half g_vh[(size_t)B_*H_*T_*64];
__device__ __half g_ctxh[(size_t)M_*D_];      // (B,T,D) fp16
__device__ __half g_wth[(size_t)4*D_*D_];     // W^T fp16: [4][N][K] (Wq pre-scaled QSCALE)

__device__ __forceinline__ float neg_inf() { return __int_as_float(0xff800000u); }

__device__ __forceinline__ float ex2f(float x) {
    float r;
    asm("ex2.approx.ftz.f32 %0, %1;" : "=f"(r) : "f"(x));
    return r;
}

__device__ __forceinline__ uint32_t packh2(float x, float y) {
    __half2 h = __floats2half2_rn(x, y);
    return *(uint32_t*)&h;
}

__device__ __forceinline__ uint32_t smem_u32(const void* p) {
    uint32_t a;
    asm("{ .reg .u64 t; cvta.to.shared.u64 t, %1; cvt.u32.u64 %0, t; }" : "=r"(a) : "l"(p));
    return a;
}

#define CP16(dst, src) \
    asm volatile("cp.async.cg.shared.global [%0], [%1], 16;" :: "r"(dst), "l"(src))
#define CP_COMMIT() asm volatile("cp.async.commit_group;" ::: "memory")
#define CP_WAIT(n)  asm volatile("cp.async.wait_group %0;" :: "n"(n) : "memory")

__device__ __forceinline__ void mma_f16(float* d, const uint32_t* a, const uint32_t* b) {
    asm volatile(
        "mma.sync.aligned.m16n8k16.row.col.f32.f16.f16.f32 "
        "{%0,%1,%2,%3}, {%4,%5,%6,%7}, {%8,%9}, {%0,%1,%2,%3};"
        : "+f"(d[0]), "+f"(d[1]), "+f"(d[2]), "+f"(d[3])
        : "r"(a[0]), "r"(a[1]), "r"(a[2]), "r"(a[3]), "r"(b[0]), "r"(b[1]));
}

__device__ __forceinline__ void ldsm4(uint32_t* r, uint32_t addr) {
    asm volatile("ldmatrix.sync.aligned.m8n8.x4.shared.b16 {%0,%1,%2,%3}, [%4];"
        : "=r"(r[0]), "=r"(r[1]), "=r"(r[2]), "=r"(r[3]) : "r"(addr));
}
__device__ __forceinline__ void ldsm4t(uint32_t* r, uint32_t addr) {
    asm volatile("ldmatrix.sync.aligned.m8n8.x4.trans.shared.b16 {%0,%1,%2,%3}, [%4];"
        : "=r"(r[0]), "=r"(r[1]), "=r"(r[2]), "=r"(r[3]) : "r"(addr));
}

// ---------------------------------------------------------------------------
// x -> fp16
// ---------------------------------------------------------------------------
__global__ void __launch_bounds__(256) convert_x(const float* __restrict__ x)
{
    const size_t i = ((size_t)blockIdx.x * 256 + threadIdx.x) * 8;
    float4 a = *(const float4*)(x + i);
    float4 b = *(const float4*)(x + i + 4);
    uint4 o;
    o.x = packh2(a.x, a.y); o.y = packh2(a.z, a.w);
    o.z = packh2(b.x, b.y); o.w = packh2(b.z, b.w);
    *(uint4*)(g_xh + i) = o;
}

// ---------------------------------------------------------------------------
// Weight transpose + fp16 round (Wq pre-scaled by QSCALE)
// ---------------------------------------------------------------------------
__global__ void __launch_bounds__(256) transpose_w(
    const float* __restrict__ W0, const float* __restrict__ W1,
    const float* __restrict__ W2, const float* __restrict__ W3)
{
    __shared__ float tile[32][33];
    const int z = blockIdx.z;
    const float* W = z == 0 ? W0 : z == 1 ? W1 : z == 2 ? W2 : W3;
    const float sc = (z == 0) ? QSCALE : 1.f;
    __half* out = g_wth + (size_t)z * D_ * D_;
    const int k0 = blockIdx.x * 32, n0 = blockIdx.y * 32;
    const int tx = threadIdx.x & 31, ty = threadIdx.x >> 5;
#pragma unroll
    for (int i = 0; i < 32; i += 8)
        tile[ty + i][tx] = W[(size_t)(k0 + ty + i) * D_ + n0 + tx];
    __syncthreads();
#pragma unroll
    for (int i = 0; i < 32; i += 8)
        out[(size_t)(n0 + ty + i) * D_ + k0 + tx] = __float2half_rn(tile[tx][ty + i] * sc);
}

// ---------------------------------------------------------------------------
// fp16 GEMM, cp.async 2-stage, BK=64, ONE sync per K-iteration.
// BM=BN=128; 8 warps (2x4), warp tile 64x32; direct uint32 frag loads.
// smem stride 72 halves (36 words ≡ 4 mod 32 → conflict-free frag pattern).
// ---------------------------------------------------------------------------
#define GBK    64
#define GROW   72                 // halves per row (64 + 8 pad)
#define GST_H  (128*GROW)         // 9216 halves per operand per stage
#define GST_B  (2*GST_H*2)        // 36864 B per stage (A+B)
#define GEMM_DYN (2*GST_B)        // 73728

template<int MODE>
__device__ __forceinline__ void gemm_cp(
    const __half* __restrict__ A, const __half* __restrict__ Wt,
    const float* __restrict__ bias, float bscale, void* __restrict__ outv)
{
    extern __shared__ __half smh[];
    const uint32_t smb = smem_u32(smh);

    const int t    = threadIdx.x;
    const int lane = t & 31;
    const int w    = t >> 5;
    const int g    = lane >> 2;
    const int tig  = lane & 3;
    const int wm   = (w >> 2) * 64;
    const int wn   = (w & 3) * 32;
    const int m0   = blockIdx.y * 128;
    const int n0   = blockIdx.x * 128;

    float acc[4][4][4];
#pragma unroll
    for (int mt = 0; mt < 4; mt++)
#pragma unroll
        for (int nt = 0; nt < 4; nt++)
#pragma unroll
            for (int i = 0; i < 4; i++) acc[mt][nt][i] = 0.f;

    // fill stage s with K-chunk k0c: 1024 16B chunks per operand, 4 per thread
#define GFILL(s, k0c) do { \
        const uint32_t ab = smb + (s) * GST_B; \
_Pragma("unroll") \
        for (int i = 0; i < 4; i++) { \
            const int ci  = t + i * 256; \
            const int row = ci >> 3, sg = (ci & 7) * 8; \
            CP16(ab + row * (GROW * 2) + sg * 2, \
                 A  + (size_t)(m0 + row) * D_ + (k0c) + sg); \
            CP16(ab + GST_H * 2 + row * (GROW * 2) + sg * 2, \
                 Wt + (size_t)(n0 + row) * D_ + (k0c) + sg); \
        } \
    } while (0)

    GFILL(0, 0); CP_COMMIT();

    for (int kt = 0; kt < 16; kt++) {
        CP_WAIT(0);
        __syncthreads();   // single barrier: orders prev compute before refill below
        if (kt < 15) { GFILL((kt + 1) & 1, (kt + 1) * GBK); CP_COMMIT(); }

        const __half* As = smh + (kt & 1) * (2 * GST_H);
        const __half* Bs = As + GST_H;
#pragma unroll
        for (int kk = 0; kk < 4; kk++) {
            const int k = kk * 16;
            uint32_t a[4][4], b[4][2];
#pragma unroll
            for (int mt = 0; mt < 4; mt++) {
                const int r = wm + mt * 16 + g;
                a[mt][0] = *(const uint32_t*)&As[r * GROW + k + 2 * tig];
                a[mt][1] = *(const uint32_t*)&As[(r + 8) * GROW + k + 2 * tig];
                a[mt][2] = *(const uint32_t*)&As[r * GROW + k + 2 * tig + 8];
                a[mt][3] = *(const uint32_t*)&As[(r + 8) * GROW + k + 2 * tig + 8];
            }
#pragma unroll
            for (int nt = 0; nt < 4; nt++) {
                const int c = wn + nt * 8 + g;
                b[nt][0] = *(const uint32_t*)&Bs[c * GROW + k + 2 * tig];
                b[nt][1] = *(const uint32_t*)&Bs[c * GROW + k + 2 * tig + 8];
            }
#pragma unroll
            for (int mt = 0; mt < 4; mt++)
#pragma unroll
                for (int nt = 0; nt < 4; nt++)
                    mma_f16(acc[mt][nt], a[mt], b[nt]);
        }
    }
#undef GFILL

    // Epilogue
#pragma unroll
    for (int mt = 0; mt < 4; mt++) {
        const int r = m0 + wm + mt * 16 + g;
#pragma unroll
        for (int nt = 0; nt < 4; nt++) {
            const int c = n0 + wn + nt * 8 + 2 * tig;
            const float b0 = bias[c] * bscale, b1 = bias[c + 1] * bscale;
            const float v00 = acc[mt][nt][0] + b0, v01 = acc[mt][nt][1] + b1;
            const float v10 = acc[mt][nt][2] + b0, v11 = acc[mt][nt][3] + b1;
            if (MODE == 0) {
                __half* out = (__half*)outv;
                const int h = c >> 6, dd = c & 63;
                const int b0i = r >> 11, tt0 = r & (T_ - 1);
                *(uint32_t*)&out[(((size_t)(b0i * H_ + h) * T_ + tt0) << 6) + dd] =
                    packh2(v00, v01);
                const int r1 = r + 8;
                const int b1i = r1 >> 11, tt1 = r1 & (T_ - 1);
                *(uint32_t*)&out[(((size_t)(b1i * H_ + h) * T_ + tt1) << 6) + dd] =
                    packh2(v10, v11);
            } else {
                float* out = (float*)outv;
                *(float2*)&out[(size_t)r * D_ + c] = make_float2(v00, v01);
                *(float2*)&out[(size_t)(r + 8) * D_ + c] = make_float2(v10, v11);
            }
        }
    }
}

__global__ void __launch_bounds__(256) qkv_kernel(
    const float* __restrict__ bq, const float* __restrict__ bk,
    const float* __restrict__ bv)
{
    const int z = blockIdx.z;
    const __half* Wt = g_wth + (size_t)z * D_ * D_;
    const float* bias = z == 0 ? bq : z == 1 ? bk : bv;
    __half* out = z == 0 ? g_qh : z == 1 ? g_kh : g_vh;
    gemm_cp<0>(g_xh, Wt, bias, z == 0 ? QSCALE : 1.f, out);
}

__global__ void __launch_bounds__(256) oproj_kernel(
    const float* __restrict__ bo, float* __restrict__ out)
{
    gemm_cp<1>(g_ctxh, g_wth + (size_t)3 * D_ * D_, bo, 1.f, out);
}

// ---------------------------------------------------------------------------
// Flash attention: ldmatrix + register P + cp.async double buffer,
// log2-domain softmax, ONE sync per KV tile (fill moved after the barrier).
// Block: 128 queries x one (b,h); 8 warps x 16 rows; 64-key tiles.
// smem: Qs[128][72] + 2 stages x (Ks[64][72] + Vs[64][72]) = 55296 B
// ---------------------------------------------------------------------------
#define AQ_H  72
#define AKV_H 72
#define AQ_B  (128*AQ_H*2)          // 18432
#define AST_B (2*64*AKV_H*2)        // 18432 per stage (K+V)
#define AV_OFF (64*AKV_H*2)
#define ATTN_SMEM (AQ_B + 2*AST_B)  // 55296

__global__ void __launch_bounds__(256, 2) attn_kernel()
{
    extern __shared__ __half smh[];
    const uint32_t smb = smem_u32(smh);
    __half* Qs = smh;

    const int t    = threadIdx.x;
    const int lane = t & 31;
    const int w    = t >> 5;
    const int g    = lane >> 2;
    const int tig  = lane & 3;
    const int qb   = (int)gridDim.x - 1 - (int)blockIdx.x;   // big tiles first
    const int bh   = blockIdx.y;
    const size_t base = (size_t)bh * T_ * 64;
    const int pr   = w * 16 + g;
    const int qr   = qb * 128 + pr;

    const int mat = lane >> 3, mr = lane & 7;
    const int a_rowadd = ((mat & 1) << 3) + mr;
    const int a_koff   = (mat >> 1) << 3;
    const int b_rowadd = ((mat >> 1) << 3) + mr;
    const int b_koff   = (mat & 1) << 3;

#define KVFILL(s, kb) do { \
        const uint32_t kb_ = smb + AQ_B + (s) * AST_B; \
_Pragma("unroll") \
        for (int i = 0; i < 2; i++) { \
            const int idx = t + i * 256; \
            const int row = idx >> 3, sg = (idx & 7) * 8; \
            CP16(kb_ + row * (AKV_H * 2) + sg * 2, \
                 g_kh + base + (size_t)((kb) * 64 + row) * 64 + sg); \
            CP16(kb_ + AV_OFF + row * (AKV_H * 2) + sg * 2, \
                 g_vh + base + (size_t)((kb) * 64 + row) * 64 + sg); \
        } \
    } while (0)

    const int kbmax = 2 * qb + 1;

    KVFILL(0, 0); CP_COMMIT();

    // Stage Q (pre-scaled fp16)
#pragma unroll
    for (int i = 0; i < 4; i++) {
        const int idx = t + i * 256;
        const int r = idx >> 3, sg = (idx & 7) * 8;
        *(uint4*)&Qs[r * AQ_H + sg] =
            *(const uint4*)(g_qh + base + (size_t)(qb * 128 + r) * 64 + sg);
    }
    __syncthreads();

    uint32_t qa[4][4];
#pragma unroll
    for (int kk = 0; kk < 4; kk++)
        ldsm4(qa[kk], smb + 2 * ((w * 16 + a_rowadd) * AQ_H + kk * 16 + a_koff));

    float o[8][4];
#pragma unroll
    for (int nt = 0; nt < 8; nt++)
#pragma unroll
        for (int i = 0; i < 4; i++) o[nt][i] = 0.f;
    float m0r = neg_inf(), m1r = neg_inf(), l0 = 0.f, l1 = 0.f;

    for (int kb = 0; kb <= kbmax; kb++) {
        CP_WAIT(0);
        __syncthreads();   // single barrier: prev compute done before refill below
        if (kb < kbmax) { KVFILL((kb + 1) & 1, kb + 1); CP_COMMIT(); }

        const uint32_t ks = smb + AQ_B + (kb & 1) * AST_B;
        const uint32_t vs = ks + AV_OFF;

        // S = Q K^T   (scores in log2 domain)
        float s[8][4];
#pragma unroll
        for (int nt = 0; nt < 8; nt++)
#pragma unroll
            for (int i = 0; i < 4; i++) s[nt][i] = 0.f;
#pragma unroll
        for (int kk = 0; kk < 4; kk++) {
            const int k = kk * 16;
#pragma unroll
            for (int p = 0; p < 4; p++) {
                uint32_t kbf[4];
                ldsm4(kbf, ks + 2 * ((p * 16 + b_rowadd) * AKV_H + k + b_koff));
                mma_f16(s[2 * p],     qa[kk], kbf);
                mma_f16(s[2 * p + 1], qa[kk], kbf + 2);
            }
        }

        // Causal mask (diagonal key blocks only)
        if (kb >= 2 * qb) {
            const int r0g = qr, r1g = qr + 8;
#pragma unroll
            for (int nt = 0; nt < 8; nt++) {
                const int j0 = kb * 64 + nt * 8 + 2 * tig;
                if (j0 > r0g)     s[nt][0] = neg_inf();
                if (j0 + 1 > r0g) s[nt][1] = neg_inf();
                if (j0 > r1g)     s[nt][2] = neg_inf();
                if (j0 + 1 > r1g) s[nt][3] = neg_inf();
            }
        }

        // Online softmax (log2 domain; rows g, g+8; 4-lane shfl groups)
        float mx0 = neg_inf(), mx1 = neg_inf();
#pragma unroll
        for (int nt = 0; nt < 8; nt++) {
            mx0 = fmaxf(mx0, fmaxf(s[nt][0], s[nt][1]));
            mx1 = fmaxf(mx1, fmaxf(s[nt][2], s[nt][3]));
        }
        mx0 = fmaxf(mx0, __shfl_xor_sync(0xffffffffu, mx0, 1));
        mx0 = fmaxf(mx0, __shfl_xor_sync(0xffffffffu, mx0, 2));
        mx1 = fmaxf(mx1, __shfl_xor_sync(0xffffffffu, mx1, 1));
        mx1 = fmaxf(mx1, __shfl_xor_sync(0xffffffffu, mx1, 2));

        const float mn0 = fmaxf(m0r, mx0), mn1 = fmaxf(m1r, mx1);
        const float a0 = ex2f(m0r - mn0), a1 = ex2f(m1r - mn1);
        m0r = mn0; m1r = mn1;

        float rs0 = 0.f, rs1 = 0.f;
#pragma unroll
        for (int nt = 0; nt < 8; nt++) {
            s[nt][0] = ex2f(s[nt][0] - mn0);
            s[nt][1] = ex2f(s[nt][1] - mn0);
            s[nt][2] = ex2f(s[nt][2] - mn1);
            s[nt][3] = ex2f(s[nt][3] - mn1);
            rs0 += s[nt][0] + s[nt][1];
            rs1 += s[nt][2] + s[nt][3];
        }
        rs0 += __shfl_xor_sync(0xffffffffu, rs0, 1);
        rs0 += __shfl_xor_sync(0xffffffffu, rs0, 2);
        rs1 += __shfl_xor_sync(0xffffffffu, rs1, 1);
        rs1 += __shfl_xor_sync(0xffffffffu, rs1, 2);
        l0 = l0 * a0 + rs0;
        l1 = l1 * a1 + rs1;

#pragma unroll
        for (int nt = 0; nt < 8; nt++) {
            o[nt][0] *= a0; o[nt][1] *= a0;
            o[nt][2] *= a1; o[nt][3] *= a1;
        }

        // O += P V : P packed straight from S registers (C-frag == A-frag layout)
#pragma unroll
        for (int kk = 0; kk < 4; kk++) {
            uint32_t pa[4];
            pa[0] = packh2(s[2 * kk][0],     s[2 * kk][1]);
            pa[1] = packh2(s[2 * kk][2],     s[2 * kk][3]);
            pa[2] = packh2(s[2 * kk + 1][0], s[2 * kk + 1][1]);
            pa[3] = packh2(s[2 * kk + 1][2], s[2 * kk + 1][3]);
            const int k = kk * 16;
#pragma unroll
            for (int p = 0; p < 4; p++) {
                uint32_t vbf[4];
                ldsm4t(vbf, vs + 2 * ((k + a_rowadd) * AKV_H + p * 16 + a_koff));
                mma_f16(o[2 * p],     pa, vbf);
                mma_f16(o[2 * p + 1], pa, vbf + 2);
            }
        }
    }
#undef KVFILL

    // Epilogue: normalize + write ctx fp16 (B,T,D)
    const int bb = bh >> 4, h = bh & 15;
    const float i0 = 1.f / l0, i1 = 1.f / l1;
#pragma unroll
    for (int nt = 0; nt < 8; nt++) {
        const int d = h * 64 + nt * 8 + 2 * tig;
        *(uint32_t*)&g_ctxh[(size_t)(bb * T_ + qr) * D_ + d] =
            packh2(o[nt][0] * i0, o[nt][1] * i0);
        *(uint32_t*)&g_ctxh[(size_t)(bb * T_ + qr + 8) * D_ + d] =
            packh2(o[nt][2] * i1, o[nt][3] * i1);
    }
}

// ---------------------------------------------------------------------------
extern "C" void kernel_launch(void* const* d_in, const int* in_sizes, int n_in,
                              void* d_out, int out_size)
{
    (void)in_sizes; (void)n_in; (void)out_size;
    const float* x  = (const float*)d_in[0];
    const float* Wq = (const float*)d_in[1];
    const float* bq = (const float*)d_in[2];
    const float* Wk = (const float*)d_in[3];
    const float* bk = (const float*)d_in[4];
    const float* Wv = (const float*)d_in[5];
    const float* bv = (const float*)d_in[6];
    const float* Wo = (const float*)d_in[7];
    const float* bo = (const float*)d_in[8];
    float* out = (float*)d_out;

    convert_x<<<M_ * D_ / (256 * 8), 256>>>(x);
    transpose_w<<<dim3(D_ / 32, D_ / 32, 4), 256>>>(Wq, Wk, Wv, Wo);

    cudaFuncSetAttribute(qkv_kernel, cudaFuncAttributeMaxDynamicSharedMemorySize, GEMM_DYN);
    qkv_kernel<<<dim3(D_ / 128, M_ / 128, 3), 256, GEMM_DYN>>>(bq, bk, bv);

    cudaFuncSetAttribute(attn_kernel, cudaFuncAttributeMaxDynamicSharedMemorySize, ATTN_SMEM);
    attn_kernel<<<dim3(T_ / 128, B_ * H_), 256, ATTN_SMEM>>>();

    cudaFuncSetAttribute(oproj_kernel, cudaFuncAttributeMaxDynamicSharedMemorySize, GEMM_DYN);
    oproj_kernel<<<dim3(D_ / 128, M_ / 128), 256, GEMM_DYN>>>(bo, out);
}